// round 13
// baseline (speedup 1.0000x reference)
#include <cuda_runtime.h>
#include <cuda_fp16.h>
#include <cstdint>

#define NCC   100000   // n_coarse
#define NFF   400000   // n_fine
#define CDIM  64
#define EPMAX 1200000
#define ECMAX 1600000
#define EUMAX 1200000

typedef unsigned long long u64;

// ---------------- scratch ----------------
__device__ __half g_a [(size_t)NCC * CDIM];   // cycled fp16 feature buffer (xc / h / h2)
__device__ __half g_t [(size_t)NCC * CDIM];   // fp16 neighbor-transformed features
__device__ float  g_h [(size_t)NCC * CDIM];   // fp32 root+bias (H) buffer
__device__ __half g_xh[(size_t)NFF * CDIM];   // fp16 copy of input x
__device__ __half g_wh[2][128 * 64];          // concat(Wn,Wr) as fp16, [n][k] layout

// CSR build scratch (cnt buffer has lookback-state tail)
__device__ int  g_pool_cnt[NCC + 8 + 512];
__device__ int  g_pool_off[NCC + 4];
__device__ int  g_pool_cur[NCC];
__device__ int2 g_pool_edges[EPMAX];

__device__ int  g_conv_cnt[NCC + 8 + 512];
__device__ int  g_conv_off[NCC + 4];
__device__ int  g_conv_cur[NCC];
__device__ int2 g_conv_edges[ECMAX];

__device__ int  g_unp_cnt[NFF + 8 + 512];
__device__ int  g_unp_off[NFF + 4];
__device__ int  g_unp_cur[NFF];
__device__ int2 g_unp_edges[EUMAX];

// ---------------- helpers ----------------
__device__ __forceinline__ uint32_t f2toh2(float lo, float hi) {
    __half2 h = __floats2half2_rn(lo, hi);
    return *reinterpret_cast<uint32_t*>(&h);
}

// ---------------- small utility kernels ----------------
__global__ void hist_kernel(const int* __restrict__ dst, int* __restrict__ cnt, int E) {
    int i = (blockIdx.x * blockDim.x + threadIdx.x) * 4;
    if (i + 3 < E) {
        int4 d = *reinterpret_cast<const int4*>(dst + i);
        atomicAdd(&cnt[d.x], 1);
        atomicAdd(&cnt[d.y], 1);
        atomicAdd(&cnt[d.z], 1);
        atomicAdd(&cnt[d.w], 1);
    } else {
        for (int j = i; j < E && j < i + 4; j++) atomicAdd(&cnt[dst[j]], 1);
    }
}

// ---- single-pass exclusive scan with decoupled lookback ----
__global__ void __launch_bounds__(256) scan_lookback(
    const int* __restrict__ cnt, int* __restrict__ state,
    int* __restrict__ off, int* __restrict__ cursor, int n)
{
    __shared__ int ws[8];
    __shared__ int s_total;
    __shared__ int s_prefix;
    const int blk = blockIdx.x;
    const int tid = threadIdx.x, lane = tid & 31, wid = tid >> 5;
    const int base = blk * 1024 + tid * 4;

    int v0 = 0, v1 = 0, v2 = 0, v3 = 0;
    if (base + 3 < n) {
        int4 v = *reinterpret_cast<const int4*>(cnt + base);
        v0 = v.x; v1 = v.y; v2 = v.z; v3 = v.w;
    } else {
        if (base + 0 < n) v0 = cnt[base + 0];
        if (base + 1 < n) v1 = cnt[base + 1];
        if (base + 2 < n) v2 = cnt[base + 2];
        if (base + 3 < n) v3 = cnt[base + 3];
    }
    int s = v0 + v1 + v2 + v3;
    int p = s;
#pragma unroll
    for (int o = 1; o < 32; o <<= 1) {
        int t = __shfl_up_sync(0xffffffffu, p, o);
        if (lane >= o) p += t;
    }
    if (lane == 31) ws[wid] = p;
    __syncthreads();
    if (tid < 8) {
        int t = ws[tid];
        int q = t;
#pragma unroll
        for (int o = 1; o < 8; o <<= 1) {
            int u = __shfl_up_sync(0xffu, q, o);
            if (tid >= o) q += u;
        }
        ws[tid] = q - t;
        if (tid == 7) s_total = q;
    }
    __syncthreads();
    const int total = s_total;

    if (tid == 0) {
        if (blk == 0) {
            atomicExch(&state[0], (total << 2) | 2);
            s_prefix = 0;
        } else {
            atomicExch(&state[blk], (total << 2) | 1);
            int exc = 0;
            int j = blk - 1;
            while (j >= 0) {
                int st;
                do { st = atomicAdd(&state[j], 0); } while ((st & 3) == 0);
                exc += st >> 2;
                if ((st & 3) == 2) break;
                j--;
            }
            atomicExch(&state[blk], ((exc + total) << 2) | 2);
            s_prefix = exc;
        }
    }
    __syncthreads();

    const int excl = s_prefix + ws[wid] + (p - s);
    int o0 = excl, o1 = excl + v0, o2 = o1 + v1, o3 = o2 + v2;
    if (base + 3 < n) {
        *reinterpret_cast<int4*>(off + base) = make_int4(o0, o1, o2, o3);
    } else {
        if (base + 0 < n) off[base + 0] = o0;
        if (base + 1 < n) off[base + 1] = o1;
        if (base + 2 < n) off[base + 2] = o2;
        if (base + 3 < n) off[base + 3] = o3;
    }
    if (base + 0 < n - 1) cursor[base + 0] = o0;
    if (base + 1 < n - 1) cursor[base + 1] = o1;
    if (base + 2 < n - 1) cursor[base + 2] = o2;
    if (base + 3 < n - 1) cursor[base + 3] = o3;
}

__global__ void permute_kernel(const int* __restrict__ src, const int* __restrict__ dst,
                               const float* __restrict__ attr, int* __restrict__ cursor,
                               int2* __restrict__ edges, int E) {
    int i = (blockIdx.x * blockDim.x + threadIdx.x) * 4;
    if (i + 3 < E) {
        int4   sv = *reinterpret_cast<const int4*>(src + i);
        int4   dv = *reinterpret_cast<const int4*>(dst + i);
        float4 av = *reinterpret_cast<const float4*>(attr + i);
        int p0 = atomicAdd(&cursor[dv.x], 1);
        int p1 = atomicAdd(&cursor[dv.y], 1);
        int p2 = atomicAdd(&cursor[dv.z], 1);
        int p3 = atomicAdd(&cursor[dv.w], 1);
        edges[p0] = make_int2(sv.x, __float_as_int(av.x));
        edges[p1] = make_int2(sv.y, __float_as_int(av.y));
        edges[p2] = make_int2(sv.z, __float_as_int(av.z));
        edges[p3] = make_int2(sv.w, __float_as_int(av.w));
    } else {
        for (int j = i; j < E && j < i + 4; j++) {
            int p = atomicAdd(&cursor[dst[j]], 1);
            edges[p] = make_int2(src[j], __float_as_int(attr[j]));
        }
    }
}

// convert BOTH layers' concat(Wn, Wr) -> fp16 [n][k] in one launch
__global__ void wconvert2(const float* __restrict__ W1n, const float* __restrict__ W1r,
                          const float* __restrict__ W2n, const float* __restrict__ W2r,
                          __half* __restrict__ Wh)
{
    int idx = blockIdx.x * 256 + threadIdx.x;
    if (idx >= 2 * 128 * 64) return;
    int layer = idx >> 13;
    int r = idx & 8191;
    int n = r >> 6, k = r & 63;
    const float* Wn = layer ? W2n : W1n;
    const float* Wr = layer ? W2r : W1r;
    float v = (n < 64) ? Wn[k * 64 + n] : Wr[k * 64 + (n - 64)];
    Wh[idx] = __float2half(v);
}

// convert fp32 array -> fp16 (8 floats / thread)
__global__ void __launch_bounds__(256) xconvert(
    const float* __restrict__ src, __half* __restrict__ dst, int n8)
{
    int i = blockIdx.x * blockDim.x + threadIdx.x;
    if (i >= n8) return;
    const float4* p = reinterpret_cast<const float4*>(src) + i * 2;
    float4 a = p[0], b = p[1];
    uint4 o;
    o.x = f2toh2(a.x, a.y);
    o.y = f2toh2(a.z, a.w);
    o.z = f2toh2(b.x, b.y);
    o.w = f2toh2(b.z, b.w);
    reinterpret_cast<uint4*>(dst)[i] = o;
}

// ---------------- CSR gather over fp16 features: 8 threads/node ----------------
// INIT: start from initp (fp32) row; else zero.
// OUT_HALF: write fp16; else fp32 (STREAM -> st.cs).
template <bool INIT, bool OUT_HALF, bool STREAM>
__global__ void __launch_bounds__(256) gather_h(
    const __half* __restrict__ feat,
    const int2*   __restrict__ edges,
    const int*    __restrict__ off,
    const float*  __restrict__ initp,
    float*        __restrict__ outf,
    __half*       __restrict__ outh,
    int n)
{
    int idx = blockIdx.x * blockDim.x + threadIdx.x;
    int node = idx >> 3;
    if (node >= n) return;
    int q = (idx & 7) << 3;

    int e0 = __ldg(off + node);
    int e1 = __ldg(off + node + 1);

    float4 acc0, acc1;
    if (INIT) {
        const float* irow = initp + (size_t)node * CDIM + q;
        acc0 = *reinterpret_cast<const float4*>(irow);
        acc1 = *reinterpret_cast<const float4*>(irow + 4);
    } else {
        acc0 = make_float4(0.f, 0.f, 0.f, 0.f);
        acc1 = acc0;
    }

#define GH_ONE(SRC, WBITS)                                                          \
    {                                                                               \
        float w = __int_as_float(WBITS);                                            \
        uint4 hv = __ldg(reinterpret_cast<const uint4*>(feat + ((size_t)(SRC) << 6) + q)); \
        __half2 h0 = *reinterpret_cast<__half2*>(&hv.x);                            \
        __half2 h1 = *reinterpret_cast<__half2*>(&hv.y);                            \
        __half2 h2 = *reinterpret_cast<__half2*>(&hv.z);                            \
        __half2 h3 = *reinterpret_cast<__half2*>(&hv.w);                            \
        float2 f0 = __half22float2(h0);                                             \
        float2 f1 = __half22float2(h1);                                             \
        float2 f2 = __half22float2(h2);                                             \
        float2 f3 = __half22float2(h3);                                             \
        acc0.x = fmaf(w, f0.x, acc0.x);                                             \
        acc0.y = fmaf(w, f0.y, acc0.y);                                             \
        acc0.z = fmaf(w, f1.x, acc0.z);                                             \
        acc0.w = fmaf(w, f1.y, acc0.w);                                             \
        acc1.x = fmaf(w, f2.x, acc1.x);                                             \
        acc1.y = fmaf(w, f2.y, acc1.y);                                             \
        acc1.z = fmaf(w, f3.x, acc1.z);                                             \
        acc1.w = fmaf(w, f3.y, acc1.w);                                             \
    }

    int e = e0;
    if ((e & 1) && e < e1) {
        int2 ed = __ldg(edges + e);
        GH_ONE(ed.x, ed.y);
        e++;
    }
    for (; e + 2 <= e1; e += 2) {
        int4 ep = __ldg(reinterpret_cast<const int4*>(edges + e));  // two edges
        GH_ONE(ep.x, ep.y);
        GH_ONE(ep.z, ep.w);
    }
    if (e < e1) {
        int2 ed = __ldg(edges + e);
        GH_ONE(ed.x, ed.y);
    }
#undef GH_ONE

    if (OUT_HALF) {
        uint4 o;
        o.x = f2toh2(acc0.x, acc0.y);
        o.y = f2toh2(acc0.z, acc0.w);
        o.z = f2toh2(acc1.x, acc1.y);
        o.w = f2toh2(acc1.z, acc1.w);
        *reinterpret_cast<uint4*>(outh + ((size_t)node << 6) + q) = o;
    } else {
        float* orow = outf + (size_t)node * CDIM + q;
        if (STREAM) {
            __stcs(reinterpret_cast<float4*>(orow),     acc0);
            __stcs(reinterpret_cast<float4*>(orow + 4), acc1);
        } else {
            *reinterpret_cast<float4*>(orow)     = acc0;
            *reinterpret_cast<float4*>(orow + 4) = acc1;
        }
    }
}

// ---------------- tensor-core dual GEMM (fp16 A direct load) ----------------
#define ROWS_PER_BLK 128
#define WSTR 68

__device__ __forceinline__ void mma16816(
    float& c0, float& c1, float& c2, float& c3,
    uint32_t a0, uint32_t a1, uint32_t a2, uint32_t a3,
    uint32_t b0, uint32_t b1)
{
    asm volatile(
        "mma.sync.aligned.m16n8k16.row.col.f32.f16.f16.f32 "
        "{%0,%1,%2,%3}, {%4,%5,%6,%7}, {%8,%9}, {%0,%1,%2,%3};\n"
        : "+f"(c0), "+f"(c1), "+f"(c2), "+f"(c3)
        : "r"(a0), "r"(a1), "r"(a2), "r"(a3), "r"(b0), "r"(b1));
}

__global__ void __launch_bounds__(256, 2) dual_gemm_mma(
    const __half* __restrict__ A,     // [N][64] fp16
    const __half* __restrict__ Wh,
    const float* __restrict__ bias,
    __half* __restrict__ T,
    float*  __restrict__ H,
    int N)
{
    __shared__ __half sW[128 * WSTR];

    const int t = threadIdx.x;

#pragma unroll
    for (int i = 0; i < 8; i++) {
        int idx = t + 256 * i;
        int n = idx >> 4, kq = (idx & 15) * 4;
        uint2 v = *reinterpret_cast<const uint2*>(Wh + n * 64 + kq);
        *reinterpret_cast<uint2*>(sW + n * WSTR + kq) = v;
    }
    __syncthreads();

    const int warp = t >> 5, lane = t & 31;
    const int gid = lane >> 2, tig = lane & 3;
    const int rA = blockIdx.x * ROWS_PER_BLK + warp * 16 + gid;
    const int rB = rA + 8;
    const int rAl = (rA < N) ? rA : (N - 1);
    const int rBl = (rB < N) ? rB : (N - 1);
    const __half* Arow0 = A + (size_t)rAl * CDIM;
    const __half* Arow8 = A + (size_t)rBl * CDIM;

    float acc[16][4];
#pragma unroll
    for (int nt = 0; nt < 16; nt++)
#pragma unroll
        for (int j = 0; j < 4; j++) acc[nt][j] = 0.f;

#pragma unroll
    for (int ks = 0; ks < 4; ks++) {
        const int c = ks * 16 + tig * 2;
        uint32_t a0 = *reinterpret_cast<const uint32_t*>(Arow0 + c);
        uint32_t a1 = *reinterpret_cast<const uint32_t*>(Arow8 + c);
        uint32_t a2 = *reinterpret_cast<const uint32_t*>(Arow0 + c + 8);
        uint32_t a3 = *reinterpret_cast<const uint32_t*>(Arow8 + c + 8);

        const __half* wb = sW + ks * 16 + tig * 2 + gid * WSTR;
#pragma unroll
        for (int nt = 0; nt < 16; nt++) {
            const __half* wp = wb + nt * 8 * WSTR;
            uint32_t b0 = *reinterpret_cast<const uint32_t*>(wp);
            uint32_t b1 = *reinterpret_cast<const uint32_t*>(wp + 8);
            mma16816(acc[nt][0], acc[nt][1], acc[nt][2], acc[nt][3],
                     a0, a1, a2, a3, b0, b1);
        }
    }

#pragma unroll
    for (int nt = 0; nt < 8; nt++) {
        int col = nt * 8 + tig * 2;
        if (rA < N)
            *reinterpret_cast<uint32_t*>(T + (size_t)rA * CDIM + col) = f2toh2(acc[nt][0], acc[nt][1]);
        if (rB < N)
            *reinterpret_cast<uint32_t*>(T + (size_t)rB * CDIM + col) = f2toh2(acc[nt][2], acc[nt][3]);
    }
#pragma unroll
    for (int nt = 8; nt < 16; nt++) {
        int col = (nt - 8) * 8 + tig * 2;
        float2 bv = *reinterpret_cast<const float2*>(bias + col);
        if (rA < N) {
            float2 o; o.x = acc[nt][0] + bv.x; o.y = acc[nt][1] + bv.y;
            *reinterpret_cast<float2*>(H + (size_t)rA * CDIM + col) = o;
        }
        if (rB < N) {
            float2 o; o.x = acc[nt][2] + bv.x; o.y = acc[nt][3] + bv.y;
            *reinterpret_cast<float2*>(H + (size_t)rB * CDIM + col) = o;
        }
    }
}

// ---------------- host-side CSR build helper ----------------
static void build_csr(const int* src, const int* dst, const float* attr, int E,
                      int* cnt, int* off, int* cur, int2* edges, int nNodes,
                      cudaStream_t s)
{
    const int n1 = nNodes + 1;
    const int nb = (n1 + 1023) / 1024;
    const int stateOff = (n1 + 3) & ~3;
    int* state = cnt + stateOff;
    cudaMemsetAsync(cnt, 0, (size_t)(stateOff + nb) * sizeof(int), s);
    hist_kernel<<<(E + 1023) / 1024, 256, 0, s>>>(dst, cnt, E);
    scan_lookback<<<nb, 256, 0, s>>>(cnt, state, off, cur, n1);
    permute_kernel<<<(E + 1023) / 1024, 256, 0, s>>>(src, dst, attr, cur, edges, E);
}

// ---------------- launch ----------------
extern "C" void kernel_launch(void* const* d_in, const int* in_sizes, int n_in,
                              void* d_out, int out_size)
{
    const float* x    = (const float*)d_in[0];
    const float* W1r  = (const float*)d_in[1];
    const float* W1n  = (const float*)d_in[2];
    const float* b1   = (const float*)d_in[3];
    const float* W2r  = (const float*)d_in[4];
    const float* W2n  = (const float*)d_in[5];
    const float* b2   = (const float*)d_in[6];
    const int*   psrc = (const int*)d_in[7];
    const int*   pdst = (const int*)d_in[8];
    const float* patt = (const float*)d_in[9];
    const int*   csrc = (const int*)d_in[10];
    const int*   cdst = (const int*)d_in[11];
    const float* catt = (const float*)d_in[12];
    const int*   usrc = (const int*)d_in[13];
    const int*   udst = (const int*)d_in[14];
    const float* uatt = (const float*)d_in[15];

    const int Ep = in_sizes[7];
    const int Ec = in_sizes[10];
    const int Eu = in_sizes[13];

    float* out = (float*)d_out;

    float* hb;
    __half *ab, *tb, *wh, *xh;
    cudaGetSymbolAddress((void**)&ab, g_a);
    cudaGetSymbolAddress((void**)&tb, g_t);
    cudaGetSymbolAddress((void**)&hb, g_h);
    cudaGetSymbolAddress((void**)&wh, g_wh);
    cudaGetSymbolAddress((void**)&xh, g_xh);
    __half* w1h = wh;
    __half* w2h = wh + 128 * 64;

    int *pcnt, *poff, *pcur, *ccnt, *coff, *ccur, *ucnt, *uoff, *ucur;
    int2 *pedg, *cedg, *uedg;
    cudaGetSymbolAddress((void**)&pcnt, g_pool_cnt);
    cudaGetSymbolAddress((void**)&poff, g_pool_off);
    cudaGetSymbolAddress((void**)&pcur, g_pool_cur);
    cudaGetSymbolAddress((void**)&pedg, g_pool_edges);
    cudaGetSymbolAddress((void**)&ccnt, g_conv_cnt);
    cudaGetSymbolAddress((void**)&coff, g_conv_off);
    cudaGetSymbolAddress((void**)&ccur, g_conv_cur);
    cudaGetSymbolAddress((void**)&cedg, g_conv_edges);
    cudaGetSymbolAddress((void**)&ucnt, g_unp_cnt);
    cudaGetSymbolAddress((void**)&uoff, g_unp_off);
    cudaGetSymbolAddress((void**)&ucur, g_unp_cur);
    cudaGetSymbolAddress((void**)&uedg, g_unp_edges);

    static cudaStream_t sB = nullptr, sC = nullptr;
    static cudaEvent_t ev0 = nullptr, evB = nullptr, evC = nullptr, evX = nullptr;
    if (sB == nullptr) {
        cudaStreamCreateWithFlags(&sB, cudaStreamNonBlocking);
        cudaStreamCreateWithFlags(&sC, cudaStreamNonBlocking);
        cudaEventCreateWithFlags(&ev0, cudaEventDisableTiming);
        cudaEventCreateWithFlags(&evB, cudaEventDisableTiming);
        cudaEventCreateWithFlags(&evC, cudaEventDisableTiming);
        cudaEventCreateWithFlags(&evX, cudaEventDisableTiming);
    }

    // fork: weights + x->fp16 + conv CSR on sB; unpool CSR on sC
    cudaEventRecord(ev0, 0);
    cudaStreamWaitEvent(sB, ev0, 0);
    cudaStreamWaitEvent(sC, ev0, 0);
    wconvert2<<<64, 256, 0, sB>>>(W1n, W1r, W2n, W2r, wh);
    const int n8 = NFF * CDIM / 8;
    xconvert<<<(n8 + 255) / 256, 256, 0, sB>>>(x, xh, n8);
    cudaEventRecord(evX, sB);   // weights + xh ready
    build_csr(csrc, cdst, catt, Ec, ccnt, coff, ccur, cedg, NCC, sB);
    cudaEventRecord(evB, sB);
    build_csr(usrc, udst, uatt, Eu, ucnt, uoff, ucur, uedg, NFF, sC);
    cudaEventRecord(evC, sC);

    // critical path: pool CSR
    build_csr(psrc, pdst, patt, Ep, pcnt, poff, pcur, pedg, NCC, 0);

    const int gthreadsC = NCC * 8;
    const int gthreadsF = NFF * 8;
    const int gemmBlocks = (NCC + ROWS_PER_BLK - 1) / ROWS_PER_BLK;

    // pool: a = gather(xh)  [fp16 -> fp16]
    cudaStreamWaitEvent(0, evX, 0);
    gather_h<false, true, false><<<(gthreadsC + 255) / 256, 256>>>(
        xh, pedg, poff, nullptr, nullptr, ab, NCC);

    // layer 1: (T, H) = gemm(a); a = H + gather(T)
    dual_gemm_mma<<<gemmBlocks, 256>>>(ab, w1h, b1, tb, hb, NCC);
    cudaStreamWaitEvent(0, evB, 0);
    gather_h<true, true, false><<<(gthreadsC + 255) / 256, 256>>>(
        tb, cedg, coff, hb, nullptr, ab, NCC);

    // layer 2: (T, H) = gemm(a); a = H + gather(T)
    dual_gemm_mma<<<gemmBlocks, 256>>>(ab, w2h, b2, tb, hb, NCC);
    gather_h<true, true, false><<<(gthreadsC + 255) / 256, 256>>>(
        tb, cedg, coff, hb, nullptr, ab, NCC);

    // unpool: out = gather(a)  [fp16 -> fp32, streaming stores]
    cudaStreamWaitEvent(0, evC, 0);
    gather_h<false, false, true><<<(gthreadsF + 255) / 256, 256>>>(
        ab, uedg, uoff, nullptr, out, nullptr, NFF);
}

// round 14
// speedup vs baseline: 1.1625x; 1.1625x over previous
#include <cuda_runtime.h>
#include <cuda_fp16.h>
#include <cstdint>

#define NCC   100000   // n_coarse
#define NFF   400000   // n_fine
#define CDIM  64
#define EPMAX 1200000
#define ECMAX 1600000
#define EUMAX 1200000

typedef unsigned long long u64;

// ---------------- scratch ----------------
__device__ __half g_a [(size_t)NCC * CDIM];   // cycled fp16 feature buffer (xc / h / h2)
__device__ __half g_t [(size_t)NCC * CDIM];   // fp16 neighbor-transformed features
__device__ float  g_h [(size_t)NCC * CDIM];   // fp32 root+bias (H) buffer
__device__ __half g_xh[(size_t)NFF * CDIM];   // fp16 copy of input x
__device__ __half g_wh[2][128 * 64];          // concat(Wn,Wr) as fp16, [n][k] layout

// CSR build scratch (cnt buffer has lookback-state tail)
__device__ int  g_pool_cnt[NCC + 8 + 512];
__device__ int  g_pool_off[NCC + 4];
__device__ int  g_pool_cur[NCC];
__device__ int2 g_pool_edges[EPMAX];

__device__ int  g_conv_cnt[NCC + 8 + 512];
__device__ int  g_conv_off[NCC + 4];
__device__ int  g_conv_cur[NCC];
__device__ int2 g_conv_edges[ECMAX];

__device__ int  g_unp_cnt[NFF + 8 + 512];
__device__ int  g_unp_off[NFF + 4];
__device__ int  g_unp_cur[NFF];
__device__ int2 g_unp_edges[EUMAX];

// ---------------- helpers ----------------
__device__ __forceinline__ uint32_t f2toh2(float lo, float hi) {
    __half2 h = __floats2half2_rn(lo, hi);
    return *reinterpret_cast<uint32_t*>(&h);
}

// ---------------- small utility kernels ----------------
__global__ void zero_int(int* __restrict__ p, int n) {
    int i = (blockIdx.x * blockDim.x + threadIdx.x) * 4;
    if (i + 3 < n) {
        *reinterpret_cast<int4*>(p + i) = make_int4(0, 0, 0, 0);
    } else {
        for (int j = i; j < n && j < i + 4; j++) p[j] = 0;
    }
}

__global__ void hist_kernel(const int* __restrict__ dst, int* __restrict__ cnt, int E) {
    int i = (blockIdx.x * blockDim.x + threadIdx.x) * 4;
    if (i + 3 < E) {
        int4 d = *reinterpret_cast<const int4*>(dst + i);
        atomicAdd(&cnt[d.x], 1);
        atomicAdd(&cnt[d.y], 1);
        atomicAdd(&cnt[d.z], 1);
        atomicAdd(&cnt[d.w], 1);
    } else {
        for (int j = i; j < E && j < i + 4; j++) atomicAdd(&cnt[dst[j]], 1);
    }
}

// ---- single-pass exclusive scan with WINDOWED (warp) decoupled lookback ----
// state[blk]: (value<<2)|flag, flag 0=invalid 1=aggregate 2=inclusive-prefix.
__global__ void __launch_bounds__(256) scan_lookback(
    const int* __restrict__ cnt, int* __restrict__ state,
    int* __restrict__ off, int* __restrict__ cursor, int n)
{
    __shared__ int ws[8];
    __shared__ int s_total;
    __shared__ int s_prefix;
    const int blk = blockIdx.x;
    const int tid = threadIdx.x, lane = tid & 31, wid = tid >> 5;
    const int base = blk * 1024 + tid * 4;

    int v0 = 0, v1 = 0, v2 = 0, v3 = 0;
    if (base + 3 < n) {
        int4 v = *reinterpret_cast<const int4*>(cnt + base);
        v0 = v.x; v1 = v.y; v2 = v.z; v3 = v.w;
    } else {
        if (base + 0 < n) v0 = cnt[base + 0];
        if (base + 1 < n) v1 = cnt[base + 1];
        if (base + 2 < n) v2 = cnt[base + 2];
        if (base + 3 < n) v3 = cnt[base + 3];
    }
    int s = v0 + v1 + v2 + v3;
    int p = s;
#pragma unroll
    for (int o = 1; o < 32; o <<= 1) {
        int t = __shfl_up_sync(0xffffffffu, p, o);
        if (lane >= o) p += t;
    }
    if (lane == 31) ws[wid] = p;
    __syncthreads();
    if (tid < 8) {
        int t = ws[tid];
        int q = t;
#pragma unroll
        for (int o = 1; o < 8; o <<= 1) {
            int u = __shfl_up_sync(0xffu, q, o);
            if (tid >= o) q += u;
        }
        ws[tid] = q - t;
        if (tid == 7) s_total = q;
    }
    __syncthreads();
    const int total = s_total;

    // warp 0 does the lookback, 32 predecessors per window step
    if (tid < 32) {
        if (blk == 0) {
            if (tid == 0) {
                atomicExch(&state[0], (total << 2) | 2);
                s_prefix = 0;
            }
        } else {
            if (tid == 0) atomicExch(&state[blk], (total << 2) | 1);
            __syncwarp();
            int exc = 0;
            int j = blk - 1;
            while (true) {
                int idx = j - tid;   // tid 0 = nearest predecessor
                int st;
                do {
                    st = (idx >= 0) ? atomicAdd(&state[idx], 0) : 2;  // virtual flag2/val0
                } while (__any_sync(0xffffffffu, (st & 3) == 0));
                unsigned m2 = __ballot_sync(0xffffffffu, (st & 3) == 2);
                int first2 = (m2 == 0) ? 32 : (__ffs(m2) - 1);
                int contrib = (tid <= first2 && tid < 32) ? (st >> 2) : 0;
                if (tid > first2) contrib = 0;
#pragma unroll
                for (int o = 16; o; o >>= 1)
                    contrib += __shfl_down_sync(0xffffffffu, contrib, o);
                contrib = __shfl_sync(0xffffffffu, contrib, 0);
                exc += contrib;
                if (first2 < 32) break;
                j -= 32;
            }
            if (tid == 0) {
                atomicExch(&state[blk], ((exc + total) << 2) | 2);
                s_prefix = exc;
            }
        }
    }
    __syncthreads();

    const int excl = s_prefix + ws[wid] + (p - s);
    int o0 = excl, o1 = excl + v0, o2 = o1 + v1, o3 = o2 + v2;
    if (base + 3 < n) {
        *reinterpret_cast<int4*>(off + base) = make_int4(o0, o1, o2, o3);
    } else {
        if (base + 0 < n) off[base + 0] = o0;
        if (base + 1 < n) off[base + 1] = o1;
        if (base + 2 < n) off[base + 2] = o2;
        if (base + 3 < n) off[base + 3] = o3;
    }
    if (base + 0 < n - 1) cursor[base + 0] = o0;
    if (base + 1 < n - 1) cursor[base + 1] = o1;
    if (base + 2 < n - 1) cursor[base + 2] = o2;
    if (base + 3 < n - 1) cursor[base + 3] = o3;
}

__global__ void permute_kernel(const int* __restrict__ src, const int* __restrict__ dst,
                               const float* __restrict__ attr, int* __restrict__ cursor,
                               int2* __restrict__ edges, int E) {
    int i = (blockIdx.x * blockDim.x + threadIdx.x) * 4;
    if (i + 3 < E) {
        int4   sv = *reinterpret_cast<const int4*>(src + i);
        int4   dv = *reinterpret_cast<const int4*>(dst + i);
        float4 av = *reinterpret_cast<const float4*>(attr + i);
        int p0 = atomicAdd(&cursor[dv.x], 1);
        int p1 = atomicAdd(&cursor[dv.y], 1);
        int p2 = atomicAdd(&cursor[dv.z], 1);
        int p3 = atomicAdd(&cursor[dv.w], 1);
        edges[p0] = make_int2(sv.x, __float_as_int(av.x));
        edges[p1] = make_int2(sv.y, __float_as_int(av.y));
        edges[p2] = make_int2(sv.z, __float_as_int(av.z));
        edges[p3] = make_int2(sv.w, __float_as_int(av.w));
    } else {
        for (int j = i; j < E && j < i + 4; j++) {
            int p = atomicAdd(&cursor[dst[j]], 1);
            edges[p] = make_int2(src[j], __float_as_int(attr[j]));
        }
    }
}

// convert BOTH layers' concat(Wn, Wr) -> fp16 [n][k] in one launch
__global__ void wconvert2(const float* __restrict__ W1n, const float* __restrict__ W1r,
                          const float* __restrict__ W2n, const float* __restrict__ W2r,
                          __half* __restrict__ Wh)
{
    int idx = blockIdx.x * 256 + threadIdx.x;
    if (idx >= 2 * 128 * 64) return;
    int layer = idx >> 13;
    int r = idx & 8191;
    int n = r >> 6, k = r & 63;
    const float* Wn = layer ? W2n : W1n;
    const float* Wr = layer ? W2r : W1r;
    float v = (n < 64) ? Wn[k * 64 + n] : Wr[k * 64 + (n - 64)];
    Wh[idx] = __float2half(v);
}

// convert fp32 array -> fp16 (8 floats / thread)
__global__ void __launch_bounds__(256) xconvert(
    const float* __restrict__ src, __half* __restrict__ dst, int n8)
{
    int i = blockIdx.x * blockDim.x + threadIdx.x;
    if (i >= n8) return;
    const float4* p = reinterpret_cast<const float4*>(src) + i * 2;
    float4 a = p[0], b = p[1];
    uint4 o;
    o.x = f2toh2(a.x, a.y);
    o.y = f2toh2(a.z, a.w);
    o.z = f2toh2(b.x, b.y);
    o.w = f2toh2(b.z, b.w);
    reinterpret_cast<uint4*>(dst)[i] = o;
}

// ---------------- CSR gather over fp16 features: 8 threads/node ----------------
// INIT: start from initp (fp32) row; else zero.
// OUT_HALF: write fp16; else fp32 (STREAM -> st.cs).
template <bool INIT, bool OUT_HALF, bool STREAM>
__global__ void __launch_bounds__(256) gather_h(
    const __half* __restrict__ feat,
    const int2*   __restrict__ edges,
    const int*    __restrict__ off,
    const float*  __restrict__ initp,
    float*        __restrict__ outf,
    __half*       __restrict__ outh,
    int n)
{
    int idx = blockIdx.x * blockDim.x + threadIdx.x;
    int node = idx >> 3;
    if (node >= n) return;
    int q = (idx & 7) << 3;

    int e0 = __ldg(off + node);
    int e1 = __ldg(off + node + 1);

    float4 acc0, acc1;
    if (INIT) {
        const float* irow = initp + (size_t)node * CDIM + q;
        acc0 = *reinterpret_cast<const float4*>(irow);
        acc1 = *reinterpret_cast<const float4*>(irow + 4);
    } else {
        acc0 = make_float4(0.f, 0.f, 0.f, 0.f);
        acc1 = acc0;
    }

#pragma unroll 2
    for (int e = e0; e < e1; e++) {
        int2 ed = __ldg(edges + e);
        float w = __int_as_float(ed.y);
        uint4 hv = __ldg(reinterpret_cast<const uint4*>(feat + ((size_t)ed.x << 6) + q));
        __half2 h0 = *reinterpret_cast<__half2*>(&hv.x);
        __half2 h1 = *reinterpret_cast<__half2*>(&hv.y);
        __half2 h2 = *reinterpret_cast<__half2*>(&hv.z);
        __half2 h3 = *reinterpret_cast<__half2*>(&hv.w);
        float2 f0 = __half22float2(h0);
        float2 f1 = __half22float2(h1);
        float2 f2 = __half22float2(h2);
        float2 f3 = __half22float2(h3);
        acc0.x = fmaf(w, f0.x, acc0.x);
        acc0.y = fmaf(w, f0.y, acc0.y);
        acc0.z = fmaf(w, f1.x, acc0.z);
        acc0.w = fmaf(w, f1.y, acc0.w);
        acc1.x = fmaf(w, f2.x, acc1.x);
        acc1.y = fmaf(w, f2.y, acc1.y);
        acc1.z = fmaf(w, f3.x, acc1.z);
        acc1.w = fmaf(w, f3.y, acc1.w);
    }

    if (OUT_HALF) {
        uint4 o;
        o.x = f2toh2(acc0.x, acc0.y);
        o.y = f2toh2(acc0.z, acc0.w);
        o.z = f2toh2(acc1.x, acc1.y);
        o.w = f2toh2(acc1.z, acc1.w);
        *reinterpret_cast<uint4*>(outh + ((size_t)node << 6) + q) = o;
    } else {
        float* orow = outf + (size_t)node * CDIM + q;
        if (STREAM) {
            __stcs(reinterpret_cast<float4*>(orow),     acc0);
            __stcs(reinterpret_cast<float4*>(orow + 4), acc1);
        } else {
            *reinterpret_cast<float4*>(orow)     = acc0;
            *reinterpret_cast<float4*>(orow + 4) = acc1;
        }
    }
}

// ---------------- tensor-core dual GEMM (fp16 A direct load) ----------------
#define ROWS_PER_BLK 128
#define WSTR 68

__device__ __forceinline__ void mma16816(
    float& c0, float& c1, float& c2, float& c3,
    uint32_t a0, uint32_t a1, uint32_t a2, uint32_t a3,
    uint32_t b0, uint32_t b1)
{
    asm volatile(
        "mma.sync.aligned.m16n8k16.row.col.f32.f16.f16.f32 "
        "{%0,%1,%2,%3}, {%4,%5,%6,%7}, {%8,%9}, {%0,%1,%2,%3};\n"
        : "+f"(c0), "+f"(c1), "+f"(c2), "+f"(c3)
        : "r"(a0), "r"(a1), "r"(a2), "r"(a3), "r"(b0), "r"(b1));
}

__global__ void __launch_bounds__(256, 2) dual_gemm_mma(
    const __half* __restrict__ A,     // [N][64] fp16
    const __half* __restrict__ Wh,
    const float* __restrict__ bias,
    __half* __restrict__ T,
    float*  __restrict__ H,
    int N)
{
    __shared__ __half sW[128 * WSTR];

    const int t = threadIdx.x;

#pragma unroll
    for (int i = 0; i < 8; i++) {
        int idx = t + 256 * i;
        int n = idx >> 4, kq = (idx & 15) * 4;
        uint2 v = *reinterpret_cast<const uint2*>(Wh + n * 64 + kq);
        *reinterpret_cast<uint2*>(sW + n * WSTR + kq) = v;
    }
    __syncthreads();

    const int warp = t >> 5, lane = t & 31;
    const int gid = lane >> 2, tig = lane & 3;
    const int rA = blockIdx.x * ROWS_PER_BLK + warp * 16 + gid;
    const int rB = rA + 8;
    const int rAl = (rA < N) ? rA : (N - 1);
    const int rBl = (rB < N) ? rB : (N - 1);
    const __half* Arow0 = A + (size_t)rAl * CDIM;
    const __half* Arow8 = A + (size_t)rBl * CDIM;

    float acc[16][4];
#pragma unroll
    for (int nt = 0; nt < 16; nt++)
#pragma unroll
        for (int j = 0; j < 4; j++) acc[nt][j] = 0.f;

#pragma unroll
    for (int ks = 0; ks < 4; ks++) {
        const int c = ks * 16 + tig * 2;
        uint32_t a0 = *reinterpret_cast<const uint32_t*>(Arow0 + c);
        uint32_t a1 = *reinterpret_cast<const uint32_t*>(Arow8 + c);
        uint32_t a2 = *reinterpret_cast<const uint32_t*>(Arow0 + c + 8);
        uint32_t a3 = *reinterpret_cast<const uint32_t*>(Arow8 + c + 8);

        const __half* wb = sW + ks * 16 + tig * 2 + gid * WSTR;
#pragma unroll
        for (int nt = 0; nt < 16; nt++) {
            const __half* wp = wb + nt * 8 * WSTR;
            uint32_t b0 = *reinterpret_cast<const uint32_t*>(wp);
            uint32_t b1 = *reinterpret_cast<const uint32_t*>(wp + 8);
            mma16816(acc[nt][0], acc[nt][1], acc[nt][2], acc[nt][3],
                     a0, a1, a2, a3, b0, b1);
        }
    }

#pragma unroll
    for (int nt = 0; nt < 8; nt++) {
        int col = nt * 8 + tig * 2;
        if (rA < N)
            *reinterpret_cast<uint32_t*>(T + (size_t)rA * CDIM + col) = f2toh2(acc[nt][0], acc[nt][1]);
        if (rB < N)
            *reinterpret_cast<uint32_t*>(T + (size_t)rB * CDIM + col) = f2toh2(acc[nt][2], acc[nt][3]);
    }
#pragma unroll
    for (int nt = 8; nt < 16; nt++) {
        int col = (nt - 8) * 8 + tig * 2;
        float2 bv = *reinterpret_cast<const float2*>(bias + col);
        if (rA < N) {
            float2 o; o.x = acc[nt][0] + bv.x; o.y = acc[nt][1] + bv.y;
            *reinterpret_cast<float2*>(H + (size_t)rA * CDIM + col) = o;
        }
        if (rB < N) {
            float2 o; o.x = acc[nt][2] + bv.x; o.y = acc[nt][3] + bv.y;
            *reinterpret_cast<float2*>(H + (size_t)rB * CDIM + col) = o;
        }
    }
}

// ---------------- host-side CSR build helper (4 kernels) ----------------
static void build_csr(const int* src, const int* dst, const float* attr, int E,
                      int* cnt, int* off, int* cur, int2* edges, int nNodes,
                      cudaStream_t s)
{
    const int n1 = nNodes + 1;
    const int nb = (n1 + 1023) / 1024;
    const int stateOff = (n1 + 3) & ~3;
    int* state = cnt + stateOff;
    zero_int<<<(stateOff + nb + 1023) / 1024, 256, 0, s>>>(cnt, stateOff + nb);
    hist_kernel<<<(E + 1023) / 1024, 256, 0, s>>>(dst, cnt, E);
    scan_lookback<<<nb, 256, 0, s>>>(cnt, state, off, cur, n1);
    permute_kernel<<<(E + 1023) / 1024, 256, 0, s>>>(src, dst, attr, cur, edges, E);
}

// ---------------- launch ----------------
extern "C" void kernel_launch(void* const* d_in, const int* in_sizes, int n_in,
                              void* d_out, int out_size)
{
    const float* x    = (const float*)d_in[0];
    const float* W1r  = (const float*)d_in[1];
    const float* W1n  = (const float*)d_in[2];
    const float* b1   = (const float*)d_in[3];
    const float* W2r  = (const float*)d_in[4];
    const float* W2n  = (const float*)d_in[5];
    const float* b2   = (const float*)d_in[6];
    const int*   psrc = (const int*)d_in[7];
    const int*   pdst = (const int*)d_in[8];
    const float* patt = (const float*)d_in[9];
    const int*   csrc = (const int*)d_in[10];
    const int*   cdst = (const int*)d_in[11];
    const float* catt = (const float*)d_in[12];
    const int*   usrc = (const int*)d_in[13];
    const int*   udst = (const int*)d_in[14];
    const float* uatt = (const float*)d_in[15];

    const int Ep = in_sizes[7];
    const int Ec = in_sizes[10];
    const int Eu = in_sizes[13];

    float* out = (float*)d_out;

    float* hb;
    __half *ab, *tb, *wh, *xh;
    cudaGetSymbolAddress((void**)&ab, g_a);
    cudaGetSymbolAddress((void**)&tb, g_t);
    cudaGetSymbolAddress((void**)&hb, g_h);
    cudaGetSymbolAddress((void**)&wh, g_wh);
    cudaGetSymbolAddress((void**)&xh, g_xh);
    __half* w1h = wh;
    __half* w2h = wh + 128 * 64;

    int *pcnt, *poff, *pcur, *ccnt, *coff, *ccur, *ucnt, *uoff, *ucur;
    int2 *pedg, *cedg, *uedg;
    cudaGetSymbolAddress((void**)&pcnt, g_pool_cnt);
    cudaGetSymbolAddress((void**)&poff, g_pool_off);
    cudaGetSymbolAddress((void**)&pcur, g_pool_cur);
    cudaGetSymbolAddress((void**)&pedg, g_pool_edges);
    cudaGetSymbolAddress((void**)&ccnt, g_conv_cnt);
    cudaGetSymbolAddress((void**)&coff, g_conv_off);
    cudaGetSymbolAddress((void**)&ccur, g_conv_cur);
    cudaGetSymbolAddress((void**)&cedg, g_conv_edges);
    cudaGetSymbolAddress((void**)&ucnt, g_unp_cnt);
    cudaGetSymbolAddress((void**)&uoff, g_unp_off);
    cudaGetSymbolAddress((void**)&ucur, g_unp_cur);
    cudaGetSymbolAddress((void**)&uedg, g_unp_edges);

    static cudaStream_t sB = nullptr, sC = nullptr;
    static cudaEvent_t ev0 = nullptr, evB = nullptr, evC = nullptr, evX = nullptr;
    if (sB == nullptr) {
        cudaStreamCreateWithFlags(&sB, cudaStreamNonBlocking);
        cudaStreamCreateWithFlags(&sC, cudaStreamNonBlocking);
        cudaEventCreateWithFlags(&ev0, cudaEventDisableTiming);
        cudaEventCreateWithFlags(&evB, cudaEventDisableTiming);
        cudaEventCreateWithFlags(&evC, cudaEventDisableTiming);
        cudaEventCreateWithFlags(&evX, cudaEventDisableTiming);
    }

    // weight conversion: one launch for both layers
    wconvert2<<<64, 256>>>(W1n, W1r, W2n, W2r, wh);

    // fork: x->fp16 + conv CSR on sB; unpool CSR on sC
    cudaEventRecord(ev0, 0);
    cudaStreamWaitEvent(sB, ev0, 0);
    cudaStreamWaitEvent(sC, ev0, 0);
    const int n8 = NFF * CDIM / 8;
    xconvert<<<(n8 + 255) / 256, 256, 0, sB>>>(x, xh, n8);
    cudaEventRecord(evX, sB);
    build_csr(csrc, cdst, catt, Ec, ccnt, coff, ccur, cedg, NCC, sB);
    cudaEventRecord(evB, sB);
    build_csr(usrc, udst, uatt, Eu, ucnt, uoff, ucur, uedg, NFF, sC);
    cudaEventRecord(evC, sC);

    // critical path: pool CSR
    build_csr(psrc, pdst, patt, Ep, pcnt, poff, pcur, pedg, NCC, 0);

    const int gthreadsC = NCC * 8;
    const int gthreadsF = NFF * 8;
    const int gemmBlocks = (NCC + ROWS_PER_BLK - 1) / ROWS_PER_BLK;

    // pool: a = gather(xh)  [fp16 -> fp16]
    cudaStreamWaitEvent(0, evX, 0);
    gather_h<false, true, false><<<(gthreadsC + 255) / 256, 256>>>(
        xh, pedg, poff, nullptr, nullptr, ab, NCC);

    // layer 1: (T, H) = gemm(a); a = H + gather(T)
    dual_gemm_mma<<<gemmBlocks, 256>>>(ab, w1h, b1, tb, hb, NCC);
    cudaStreamWaitEvent(0, evB, 0);
    gather_h<true, true, false><<<(gthreadsC + 255) / 256, 256>>>(
        tb, cedg, coff, hb, nullptr, ab, NCC);

    // layer 2: (T, H) = gemm(a); a = H + gather(T)
    dual_gemm_mma<<<gemmBlocks, 256>>>(ab, w2h, b2, tb, hb, NCC);
    gather_h<true, true, false><<<(gthreadsC + 255) / 256, 256>>>(
        tb, cedg, coff, hb, nullptr, ab, NCC);

    // unpool: out = gather(a)  [fp16 -> fp32, streaming stores]
    cudaStreamWaitEvent(0, evC, 0);
    gather_h<false, false, true><<<(gthreadsF + 255) / 256, 256>>>(
        ab, uedg, uoff, nullptr, out, nullptr, NFF);
}

// round 15
// speedup vs baseline: 1.1733x; 1.0093x over previous
#include <cuda_runtime.h>
#include <cuda_fp16.h>
#include <cstdint>

#define NCC   100000   // n_coarse
#define NFF   400000   // n_fine
#define CDIM  64
#define EPMAX 1200000
#define ECMAX 1600000
#define EUMAX 1200000

typedef unsigned long long u64;

// ---------------- scratch ----------------
__device__ __half g_a [(size_t)NCC * CDIM];   // cycled fp16 feature buffer (xc / h / h2)
__device__ __half g_t [(size_t)NCC * CDIM];   // fp16 neighbor-transformed features
__device__ float  g_h [(size_t)NCC * CDIM];   // fp32 root+bias (H) buffer
__device__ __half g_wh[2][128 * 64];          // concat(Wn,Wr) as fp16, [n][k] layout

// CSR build scratch (cnt buffer has lookback-state tail)
__device__ int  g_pool_cnt[NCC + 8 + 512];
__device__ int  g_pool_off[NCC + 4];
__device__ int  g_pool_cur[NCC];
__device__ int2 g_pool_edges[EPMAX];

__device__ int  g_conv_cnt[NCC + 8 + 512];
__device__ int  g_conv_off[NCC + 4];
__device__ int  g_conv_cur[NCC];
__device__ int2 g_conv_edges[ECMAX];

__device__ int  g_unp_cnt[NFF + 8 + 512];
__device__ int  g_unp_off[NFF + 4];
__device__ int  g_unp_cur[NFF];
__device__ int2 g_unp_edges[EUMAX];

// ---------------- helpers ----------------
__device__ __forceinline__ uint32_t f2toh2(float lo, float hi) {
    __half2 h = __floats2half2_rn(lo, hi);
    return *reinterpret_cast<uint32_t*>(&h);
}

// ---------------- small utility kernels ----------------
__global__ void zero_int(int* __restrict__ p, int n) {
    int i = (blockIdx.x * blockDim.x + threadIdx.x) * 4;
    if (i + 3 < n) {
        *reinterpret_cast<int4*>(p + i) = make_int4(0, 0, 0, 0);
    } else {
        for (int j = i; j < n && j < i + 4; j++) p[j] = 0;
    }
}

__global__ void hist_kernel(const int* __restrict__ dst, int* __restrict__ cnt, int E) {
    int i = (blockIdx.x * blockDim.x + threadIdx.x) * 4;
    if (i + 3 < E) {
        int4 d = *reinterpret_cast<const int4*>(dst + i);
        atomicAdd(&cnt[d.x], 1);
        atomicAdd(&cnt[d.y], 1);
        atomicAdd(&cnt[d.z], 1);
        atomicAdd(&cnt[d.w], 1);
    } else {
        for (int j = i; j < E && j < i + 4; j++) atomicAdd(&cnt[dst[j]], 1);
    }
}

// ---- single-pass exclusive scan with WINDOWED (warp) decoupled lookback ----
__global__ void __launch_bounds__(256) scan_lookback(
    const int* __restrict__ cnt, int* __restrict__ state,
    int* __restrict__ off, int* __restrict__ cursor, int n)
{
    __shared__ int ws[8];
    __shared__ int s_total;
    __shared__ int s_prefix;
    const int blk = blockIdx.x;
    const int tid = threadIdx.x, lane = tid & 31, wid = tid >> 5;
    const int base = blk * 1024 + tid * 4;

    int v0 = 0, v1 = 0, v2 = 0, v3 = 0;
    if (base + 3 < n) {
        int4 v = *reinterpret_cast<const int4*>(cnt + base);
        v0 = v.x; v1 = v.y; v2 = v.z; v3 = v.w;
    } else {
        if (base + 0 < n) v0 = cnt[base + 0];
        if (base + 1 < n) v1 = cnt[base + 1];
        if (base + 2 < n) v2 = cnt[base + 2];
        if (base + 3 < n) v3 = cnt[base + 3];
    }
    int s = v0 + v1 + v2 + v3;
    int p = s;
#pragma unroll
    for (int o = 1; o < 32; o <<= 1) {
        int t = __shfl_up_sync(0xffffffffu, p, o);
        if (lane >= o) p += t;
    }
    if (lane == 31) ws[wid] = p;
    __syncthreads();
    if (tid < 8) {
        int t = ws[tid];
        int q = t;
#pragma unroll
        for (int o = 1; o < 8; o <<= 1) {
            int u = __shfl_up_sync(0xffu, q, o);
            if (tid >= o) q += u;
        }
        ws[tid] = q - t;
        if (tid == 7) s_total = q;
    }
    __syncthreads();
    const int total = s_total;

    if (tid < 32) {
        if (blk == 0) {
            if (tid == 0) {
                atomicExch(&state[0], (total << 2) | 2);
                s_prefix = 0;
            }
        } else {
            if (tid == 0) atomicExch(&state[blk], (total << 2) | 1);
            __syncwarp();
            int exc = 0;
            int j = blk - 1;
            while (true) {
                int idx = j - tid;
                int st;
                do {
                    st = (idx >= 0) ? atomicAdd(&state[idx], 0) : 2;
                } while (__any_sync(0xffffffffu, (st & 3) == 0));
                unsigned m2 = __ballot_sync(0xffffffffu, (st & 3) == 2);
                int first2 = (m2 == 0) ? 32 : (__ffs(m2) - 1);
                int contrib = (tid <= first2) ? (st >> 2) : 0;
#pragma unroll
                for (int o = 16; o; o >>= 1)
                    contrib += __shfl_down_sync(0xffffffffu, contrib, o);
                contrib = __shfl_sync(0xffffffffu, contrib, 0);
                exc += contrib;
                if (first2 < 32) break;
                j -= 32;
            }
            if (tid == 0) {
                atomicExch(&state[blk], ((exc + total) << 2) | 2);
                s_prefix = exc;
            }
        }
    }
    __syncthreads();

    const int excl = s_prefix + ws[wid] + (p - s);
    int o0 = excl, o1 = excl + v0, o2 = o1 + v1, o3 = o2 + v2;
    if (base + 3 < n) {
        *reinterpret_cast<int4*>(off + base) = make_int4(o0, o1, o2, o3);
    } else {
        if (base + 0 < n) off[base + 0] = o0;
        if (base + 1 < n) off[base + 1] = o1;
        if (base + 2 < n) off[base + 2] = o2;
        if (base + 3 < n) off[base + 3] = o3;
    }
    if (base + 0 < n - 1) cursor[base + 0] = o0;
    if (base + 1 < n - 1) cursor[base + 1] = o1;
    if (base + 2 < n - 1) cursor[base + 2] = o2;
    if (base + 3 < n - 1) cursor[base + 3] = o3;
}

__global__ void permute_kernel(const int* __restrict__ src, const int* __restrict__ dst,
                               const float* __restrict__ attr, int* __restrict__ cursor,
                               int2* __restrict__ edges, int E) {
    int i = (blockIdx.x * blockDim.x + threadIdx.x) * 4;
    if (i + 3 < E) {
        int4   sv = *reinterpret_cast<const int4*>(src + i);
        int4   dv = *reinterpret_cast<const int4*>(dst + i);
        float4 av = *reinterpret_cast<const float4*>(attr + i);
        int p0 = atomicAdd(&cursor[dv.x], 1);
        int p1 = atomicAdd(&cursor[dv.y], 1);
        int p2 = atomicAdd(&cursor[dv.z], 1);
        int p3 = atomicAdd(&cursor[dv.w], 1);
        edges[p0] = make_int2(sv.x, __float_as_int(av.x));
        edges[p1] = make_int2(sv.y, __float_as_int(av.y));
        edges[p2] = make_int2(sv.z, __float_as_int(av.z));
        edges[p3] = make_int2(sv.w, __float_as_int(av.w));
    } else {
        for (int j = i; j < E && j < i + 4; j++) {
            int p = atomicAdd(&cursor[dst[j]], 1);
            edges[p] = make_int2(src[j], __float_as_int(attr[j]));
        }
    }
}

// convert BOTH layers' concat(Wn, Wr) -> fp16 [n][k] in one launch
__global__ void wconvert2(const float* __restrict__ W1n, const float* __restrict__ W1r,
                          const float* __restrict__ W2n, const float* __restrict__ W2r,
                          __half* __restrict__ Wh)
{
    int idx = blockIdx.x * 256 + threadIdx.x;
    if (idx >= 2 * 128 * 64) return;
    int layer = idx >> 13;
    int r = idx & 8191;
    int n = r >> 6, k = r & 63;
    const float* Wn = layer ? W2n : W1n;
    const float* Wr = layer ? W2r : W1r;
    float v = (n < 64) ? Wn[k * 64 + n] : Wr[k * 64 + (n - 64)];
    Wh[idx] = __float2half(v);
}

// ---------------- CSR gather over fp32 features -> fp16 out (pool) ----------------
__global__ void __launch_bounds__(256) gather_f32(
    const float* __restrict__ feat,
    const int2*  __restrict__ edges,
    const int*   __restrict__ off,
    __half*      __restrict__ outh,
    int n)
{
    int idx = blockIdx.x * blockDim.x + threadIdx.x;
    int node = idx >> 3;
    if (node >= n) return;
    int q = (idx & 7) << 3;

    int e0 = __ldg(off + node);
    int e1 = __ldg(off + node + 1);

    float4 acc0 = make_float4(0.f, 0.f, 0.f, 0.f);
    float4 acc1 = acc0;

#pragma unroll 2
    for (int e = e0; e < e1; e++) {
        int2 ed = __ldg(edges + e);
        float w = __int_as_float(ed.y);
        const float4* p = reinterpret_cast<const float4*>(feat + ((size_t)ed.x << 6) + q);
        float4 v0 = __ldg(p);
        float4 v1 = __ldg(p + 1);
        acc0.x = fmaf(w, v0.x, acc0.x);
        acc0.y = fmaf(w, v0.y, acc0.y);
        acc0.z = fmaf(w, v0.z, acc0.z);
        acc0.w = fmaf(w, v0.w, acc0.w);
        acc1.x = fmaf(w, v1.x, acc1.x);
        acc1.y = fmaf(w, v1.y, acc1.y);
        acc1.z = fmaf(w, v1.z, acc1.z);
        acc1.w = fmaf(w, v1.w, acc1.w);
    }

    uint4 o;
    o.x = f2toh2(acc0.x, acc0.y);
    o.y = f2toh2(acc0.z, acc0.w);
    o.z = f2toh2(acc1.x, acc1.y);
    o.w = f2toh2(acc1.z, acc1.w);
    *reinterpret_cast<uint4*>(outh + ((size_t)node << 6) + q) = o;
}

// ---------------- CSR gather over fp16 features: 8 threads/node ----------------
template <bool INIT, bool OUT_HALF, bool STREAM>
__global__ void __launch_bounds__(256) gather_h(
    const __half* __restrict__ feat,
    const int2*   __restrict__ edges,
    const int*    __restrict__ off,
    const float*  __restrict__ initp,
    float*        __restrict__ outf,
    __half*       __restrict__ outh,
    int n)
{
    int idx = blockIdx.x * blockDim.x + threadIdx.x;
    int node = idx >> 3;
    if (node >= n) return;
    int q = (idx & 7) << 3;

    int e0 = __ldg(off + node);
    int e1 = __ldg(off + node + 1);

    float4 acc0, acc1;
    if (INIT) {
        const float* irow = initp + (size_t)node * CDIM + q;
        acc0 = *reinterpret_cast<const float4*>(irow);
        acc1 = *reinterpret_cast<const float4*>(irow + 4);
    } else {
        acc0 = make_float4(0.f, 0.f, 0.f, 0.f);
        acc1 = acc0;
    }

#pragma unroll 2
    for (int e = e0; e < e1; e++) {
        int2 ed = __ldg(edges + e);
        float w = __int_as_float(ed.y);
        uint4 hv = __ldg(reinterpret_cast<const uint4*>(feat + ((size_t)ed.x << 6) + q));
        __half2 h0 = *reinterpret_cast<__half2*>(&hv.x);
        __half2 h1 = *reinterpret_cast<__half2*>(&hv.y);
        __half2 h2 = *reinterpret_cast<__half2*>(&hv.z);
        __half2 h3 = *reinterpret_cast<__half2*>(&hv.w);
        float2 f0 = __half22float2(h0);
        float2 f1 = __half22float2(h1);
        float2 f2 = __half22float2(h2);
        float2 f3 = __half22float2(h3);
        acc0.x = fmaf(w, f0.x, acc0.x);
        acc0.y = fmaf(w, f0.y, acc0.y);
        acc0.z = fmaf(w, f1.x, acc0.z);
        acc0.w = fmaf(w, f1.y, acc0.w);
        acc1.x = fmaf(w, f2.x, acc1.x);
        acc1.y = fmaf(w, f2.y, acc1.y);
        acc1.z = fmaf(w, f3.x, acc1.z);
        acc1.w = fmaf(w, f3.y, acc1.w);
    }

    if (OUT_HALF) {
        uint4 o;
        o.x = f2toh2(acc0.x, acc0.y);
        o.y = f2toh2(acc0.z, acc0.w);
        o.z = f2toh2(acc1.x, acc1.y);
        o.w = f2toh2(acc1.z, acc1.w);
        *reinterpret_cast<uint4*>(outh + ((size_t)node << 6) + q) = o;
    } else {
        float* orow = outf + (size_t)node * CDIM + q;
        if (STREAM) {
            __stcs(reinterpret_cast<float4*>(orow),     acc0);
            __stcs(reinterpret_cast<float4*>(orow + 4), acc1);
        } else {
            *reinterpret_cast<float4*>(orow)     = acc0;
            *reinterpret_cast<float4*>(orow + 4) = acc1;
        }
    }
}

// ---------------- tensor-core dual GEMM (fp16 A direct load) ----------------
#define ROWS_PER_BLK 128
#define WSTR 68

__device__ __forceinline__ void mma16816(
    float& c0, float& c1, float& c2, float& c3,
    uint32_t a0, uint32_t a1, uint32_t a2, uint32_t a3,
    uint32_t b0, uint32_t b1)
{
    asm volatile(
        "mma.sync.aligned.m16n8k16.row.col.f32.f16.f16.f32 "
        "{%0,%1,%2,%3}, {%4,%5,%6,%7}, {%8,%9}, {%0,%1,%2,%3};\n"
        : "+f"(c0), "+f"(c1), "+f"(c2), "+f"(c3)
        : "r"(a0), "r"(a1), "r"(a2), "r"(a3), "r"(b0), "r"(b1));
}

__global__ void __launch_bounds__(256, 2) dual_gemm_mma(
    const __half* __restrict__ A,
    const __half* __restrict__ Wh,
    const float* __restrict__ bias,
    __half* __restrict__ T,
    float*  __restrict__ H,
    int N)
{
    __shared__ __half sW[128 * WSTR];

    const int t = threadIdx.x;

#pragma unroll
    for (int i = 0; i < 8; i++) {
        int idx = t + 256 * i;
        int n = idx >> 4, kq = (idx & 15) * 4;
        uint2 v = *reinterpret_cast<const uint2*>(Wh + n * 64 + kq);
        *reinterpret_cast<uint2*>(sW + n * WSTR + kq) = v;
    }
    __syncthreads();

    const int warp = t >> 5, lane = t & 31;
    const int gid = lane >> 2, tig = lane & 3;
    const int rA = blockIdx.x * ROWS_PER_BLK + warp * 16 + gid;
    const int rB = rA + 8;
    const int rAl = (rA < N) ? rA : (N - 1);
    const int rBl = (rB < N) ? rB : (N - 1);
    const __half* Arow0 = A + (size_t)rAl * CDIM;
    const __half* Arow8 = A + (size_t)rBl * CDIM;

    float acc[16][4];
#pragma unroll
    for (int nt = 0; nt < 16; nt++)
#pragma unroll
        for (int j = 0; j < 4; j++) acc[nt][j] = 0.f;

#pragma unroll
    for (int ks = 0; ks < 4; ks++) {
        const int c = ks * 16 + tig * 2;
        uint32_t a0 = *reinterpret_cast<const uint32_t*>(Arow0 + c);
        uint32_t a1 = *reinterpret_cast<const uint32_t*>(Arow8 + c);
        uint32_t a2 = *reinterpret_cast<const uint32_t*>(Arow0 + c + 8);
        uint32_t a3 = *reinterpret_cast<const uint32_t*>(Arow8 + c + 8);

        const __half* wb = sW + ks * 16 + tig * 2 + gid * WSTR;
#pragma unroll
        for (int nt = 0; nt < 16; nt++) {
            const __half* wp = wb + nt * 8 * WSTR;
            uint32_t b0 = *reinterpret_cast<const uint32_t*>(wp);
            uint32_t b1 = *reinterpret_cast<const uint32_t*>(wp + 8);
            mma16816(acc[nt][0], acc[nt][1], acc[nt][2], acc[nt][3],
                     a0, a1, a2, a3, b0, b1);
        }
    }

#pragma unroll
    for (int nt = 0; nt < 8; nt++) {
        int col = nt * 8 + tig * 2;
        if (rA < N)
            *reinterpret_cast<uint32_t*>(T + (size_t)rA * CDIM + col) = f2toh2(acc[nt][0], acc[nt][1]);
        if (rB < N)
            *reinterpret_cast<uint32_t*>(T + (size_t)rB * CDIM + col) = f2toh2(acc[nt][2], acc[nt][3]);
    }
#pragma unroll
    for (int nt = 8; nt < 16; nt++) {
        int col = (nt - 8) * 8 + tig * 2;
        float2 bv = *reinterpret_cast<const float2*>(bias + col);
        if (rA < N) {
            float2 o; o.x = acc[nt][0] + bv.x; o.y = acc[nt][1] + bv.y;
            *reinterpret_cast<float2*>(H + (size_t)rA * CDIM + col) = o;
        }
        if (rB < N) {
            float2 o; o.x = acc[nt][2] + bv.x; o.y = acc[nt][3] + bv.y;
            *reinterpret_cast<float2*>(H + (size_t)rB * CDIM + col) = o;
        }
    }
}

// ---------------- host-side CSR build helper (4 kernels) ----------------
static void build_csr(const int* src, const int* dst, const float* attr, int E,
                      int* cnt, int* off, int* cur, int2* edges, int nNodes,
                      cudaStream_t s)
{
    const int n1 = nNodes + 1;
    const int nb = (n1 + 1023) / 1024;
    const int stateOff = (n1 + 3) & ~3;
    int* state = cnt + stateOff;
    zero_int<<<(stateOff + nb + 1023) / 1024, 256, 0, s>>>(cnt, stateOff + nb);
    hist_kernel<<<(E + 1023) / 1024, 256, 0, s>>>(dst, cnt, E);
    scan_lookback<<<nb, 256, 0, s>>>(cnt, state, off, cur, n1);
    permute_kernel<<<(E + 1023) / 1024, 256, 0, s>>>(src, dst, attr, cur, edges, E);
}

// ---------------- launch ----------------
extern "C" void kernel_launch(void* const* d_in, const int* in_sizes, int n_in,
                              void* d_out, int out_size)
{
    const float* x    = (const float*)d_in[0];
    const float* W1r  = (const float*)d_in[1];
    const float* W1n  = (const float*)d_in[2];
    const float* b1   = (const float*)d_in[3];
    const float* W2r  = (const float*)d_in[4];
    const float* W2n  = (const float*)d_in[5];
    const float* b2   = (const float*)d_in[6];
    const int*   psrc = (const int*)d_in[7];
    const int*   pdst = (const int*)d_in[8];
    const float* patt = (const float*)d_in[9];
    const int*   csrc = (const int*)d_in[10];
    const int*   cdst = (const int*)d_in[11];
    const float* catt = (const float*)d_in[12];
    const int*   usrc = (const int*)d_in[13];
    const int*   udst = (const int*)d_in[14];
    const float* uatt = (const float*)d_in[15];

    const int Ep = in_sizes[7];
    const int Ec = in_sizes[10];
    const int Eu = in_sizes[13];

    float* out = (float*)d_out;

    float* hb;
    __half *ab, *tb, *wh;
    cudaGetSymbolAddress((void**)&ab, g_a);
    cudaGetSymbolAddress((void**)&tb, g_t);
    cudaGetSymbolAddress((void**)&hb, g_h);
    cudaGetSymbolAddress((void**)&wh, g_wh);
    __half* w1h = wh;
    __half* w2h = wh + 128 * 64;

    int *pcnt, *poff, *pcur, *ccnt, *coff, *ccur, *ucnt, *uoff, *ucur;
    int2 *pedg, *cedg, *uedg;
    cudaGetSymbolAddress((void**)&pcnt, g_pool_cnt);
    cudaGetSymbolAddress((void**)&poff, g_pool_off);
    cudaGetSymbolAddress((void**)&pcur, g_pool_cur);
    cudaGetSymbolAddress((void**)&pedg, g_pool_edges);
    cudaGetSymbolAddress((void**)&ccnt, g_conv_cnt);
    cudaGetSymbolAddress((void**)&coff, g_conv_off);
    cudaGetSymbolAddress((void**)&ccur, g_conv_cur);
    cudaGetSymbolAddress((void**)&cedg, g_conv_edges);
    cudaGetSymbolAddress((void**)&ucnt, g_unp_cnt);
    cudaGetSymbolAddress((void**)&uoff, g_unp_off);
    cudaGetSymbolAddress((void**)&ucur, g_unp_cur);
    cudaGetSymbolAddress((void**)&uedg, g_unp_edges);

    static cudaStream_t sB = nullptr, sC = nullptr;
    static cudaEvent_t ev0 = nullptr, evB = nullptr, evC = nullptr;
    if (sB == nullptr) {
        cudaStreamCreateWithFlags(&sB, cudaStreamNonBlocking);
        cudaStreamCreateWithFlags(&sC, cudaStreamNonBlocking);
        cudaEventCreateWithFlags(&ev0, cudaEventDisableTiming);
        cudaEventCreateWithFlags(&evB, cudaEventDisableTiming);
        cudaEventCreateWithFlags(&evC, cudaEventDisableTiming);
    }

    // weight conversion: one launch for both layers
    wconvert2<<<64, 256>>>(W1n, W1r, W2n, W2r, wh);

    // fork: conv CSR on sB; unpool CSR on sC
    cudaEventRecord(ev0, 0);
    cudaStreamWaitEvent(sB, ev0, 0);
    cudaStreamWaitEvent(sC, ev0, 0);
    build_csr(csrc, cdst, catt, Ec, ccnt, coff, ccur, cedg, NCC, sB);
    cudaEventRecord(evB, sB);
    build_csr(usrc, udst, uatt, Eu, ucnt, uoff, ucur, uedg, NFF, sC);
    cudaEventRecord(evC, sC);

    // critical path: pool CSR
    build_csr(psrc, pdst, patt, Ep, pcnt, poff, pcur, pedg, NCC, 0);

    const int gthreadsC = NCC * 8;
    const int gthreadsF = NFF * 8;
    const int gemmBlocks = (NCC + ROWS_PER_BLK - 1) / ROWS_PER_BLK;

    // pool: a = gather(x fp32)  [fp32 -> fp16]
    gather_f32<<<(gthreadsC + 255) / 256, 256>>>(x, pedg, poff, ab, NCC);

    // layer 1: (T, H) = gemm(a); a = H + gather(T)
    dual_gemm_mma<<<gemmBlocks, 256>>>(ab, w1h, b1, tb, hb, NCC);
    cudaStreamWaitEvent(0, evB, 0);
    gather_h<true, true, false><<<(gthreadsC + 255) / 256, 256>>>(
        tb, cedg, coff, hb, nullptr, ab, NCC);

    // layer 2: (T, H) = gemm(a); a = H + gather(T)
    dual_gemm_mma<<<gemmBlocks, 256>>>(ab, w2h, b2, tb, hb, NCC);
    gather_h<true, true, false><<<(gthreadsC + 255) / 256, 256>>>(
        tb, cedg, coff, hb, nullptr, ab, NCC);

    // unpool: out = gather(a)  [fp16 -> fp32, streaming stores]
    cudaStreamWaitEvent(0, evC, 0);
    gather_h<false, false, true><<<(gthreadsF + 255) / 256, 256>>>(
        ab, uedg, uoff, nullptr, out, nullptr, NFF);
}